// round 1
// baseline (speedup 1.0000x reference)
#include <cuda_runtime.h>
#include <cstdint>

// Table size is fixed by the problem (4,194,304 slots). Scratch for the
// per-slot minimum winning row index. Persistent across graph replays, but
// every slot that is ever READ (only indexed slots) is re-initialized by
// k_scatter on every replay -> deterministic.
#define TABLE_SIZE_MAX 4194304
__device__ int g_min_row[TABLE_SIZE_MAX];

// ---------------------------------------------------------------------------
// Kernel 1: init outputs from inputs (full table copy + scores + longevity)
// ---------------------------------------------------------------------------
__global__ void k_init(const float* __restrict__ trust_table,
                       const float* __restrict__ trust_scores,
                       const int*   __restrict__ longevity,
                       float* __restrict__ out_table,
                       float* __restrict__ out_scores,
                       float* __restrict__ out_long,
                       int T) {
    int t = blockIdx.x * blockDim.x + threadIdx.x;
    if (t >= T) return;
    out_scores[t] = trust_scores[t];
    out_long[t]   = (float)longevity[t];
    const float4* src = reinterpret_cast<const float4*>(trust_table) + (size_t)t * 2;
    float4*       dst = reinterpret_cast<float4*>(out_table)        + (size_t)t * 2;
    dst[0] = src[0];
    dst[1] = src[1];
}

// ---------------------------------------------------------------------------
// Kernel 2: scatter-max scores, longevity counts, sentinel-init min_row
// All values are non-negative floats in [0,1), so integer-bit atomicMax
// preserves float ordering.
// ---------------------------------------------------------------------------
__global__ void k_scatter(const float* __restrict__ surv,
                          const int*   __restrict__ indices,
                          float* __restrict__ out_scores,
                          float* __restrict__ out_long,
                          int B) {
    int b = blockIdx.x * blockDim.x + threadIdx.x;
    if (b >= B) return;
    int i = indices[b];
    g_min_row[i] = 0x7FFFFFFF;                   // benign race: same value
    atomicMax(reinterpret_cast<int*>(out_scores) + i, __float_as_int(surv[b]));
    atomicAdd(out_long + i, 1.0f);               // exact for small counts
}

// ---------------------------------------------------------------------------
// Kernel 3: query gather + winner election (first row that strictly beats
// the old score and attains the final score -> min row index per slot)
// ---------------------------------------------------------------------------
__global__ void k_winner(const float* __restrict__ surv,
                         const int*   __restrict__ indices,
                         const float* __restrict__ old_scores,  // input trust_scores
                         const float* __restrict__ new_scores,  // out_scores (final)
                         float* __restrict__ query,
                         int B) {
    int b = blockIdx.x * blockDim.x + threadIdx.x;
    if (b >= B) return;
    int i  = indices[b];
    float s = surv[b];
    float f = new_scores[i];
    query[b] = f;
    if (s > old_scores[i] && s >= f) {
        atomicMin(&g_min_row[i], b);
    }
}

// ---------------------------------------------------------------------------
// Kernel 4: winner rows overwrite their table slot
// ---------------------------------------------------------------------------
__global__ void k_write(const float* __restrict__ residues,
                        const int*   __restrict__ indices,
                        float* __restrict__ out_table,
                        int B) {
    int b = blockIdx.x * blockDim.x + threadIdx.x;
    if (b >= B) return;
    int i = indices[b];
    if (g_min_row[i] == b) {
        const float4* src = reinterpret_cast<const float4*>(residues) + (size_t)b * 2;
        float4*       dst = reinterpret_cast<float4*>(out_table)      + (size_t)i * 2;
        dst[0] = src[0];
        dst[1] = src[1];
    }
}

// ---------------------------------------------------------------------------
// Launch.  Input order (metadata): residues[B*8] f32, survivorship[B] f32,
// trust_table[T*8] f32, trust_scores[T] f32, longevity[T] i32, indices[B] i32.
// Output (single f32 buffer): query[B] | new_table[T*8] | new_scores[T] |
// new_longevity[T] (as float).
// ---------------------------------------------------------------------------
extern "C" void kernel_launch(void* const* d_in, const int* in_sizes, int n_in,
                              void* d_out, int out_size) {
    const float* residues     = (const float*)d_in[0];
    const float* survivorship = (const float*)d_in[1];
    const float* trust_table  = (const float*)d_in[2];
    const float* trust_scores = (const float*)d_in[3];
    const int*   longevity    = (const int*)  d_in[4];
    const int*   indices      = (const int*)  d_in[5];

    const int B = in_sizes[1];          // 131072
    const int T = in_sizes[3];          // 4194304

    float* out        = (float*)d_out;
    float* out_query  = out;                                  // [B]
    float* out_table  = out + B;                              // [T*8]
    float* out_scores = out + B + (size_t)T * 8;              // [T]
    float* out_long   = out + B + (size_t)T * 8 + T;          // [T]

    const int TPB = 256;
    const int gT = (T + TPB - 1) / TPB;
    const int gB = (B + TPB - 1) / TPB;

    k_init   <<<gT, TPB>>>(trust_table, trust_scores, longevity,
                           out_table, out_scores, out_long, T);
    k_scatter<<<gB, TPB>>>(survivorship, indices, out_scores, out_long, B);
    k_winner <<<gB, TPB>>>(survivorship, indices, trust_scores, out_scores,
                           out_query, B);
    k_write  <<<gB, TPB>>>(residues, indices, out_table, B);
}